// round 1
// baseline (speedup 1.0000x reference)
#include <cuda_runtime.h>

#define S   32768          // 32*32*32 spatial
#define NB  2              // batch
#define CIN 64
#define CM  32             // mid channels
#define KCH 216            // dynamic kernel channels
#define NG  8              // groups
#define CPG 8              // channels per group (64/8)

// ---------------- scratch (device globals; allocation-free) ----------------
__device__ float g_a1[NB * CM  * S];   // after cv1+bn+relu
__device__ float g_a2[NB * CM  * S];   // after dw5+bn
__device__ float g_wk[NB * KCH * S];   // cv4 output (pre-GN)
__device__ float g_y [NB * CIN * S];   // after SKA + bn + residual
__device__ float g_h [NB * 128 * S];   // FFN hidden
__device__ float g_sum[NB * NG];
__device__ float g_sq [NB * NG];
__device__ float g_mu [NB * NG];
__device__ float g_rstd[NB * NG];

// ---------------- k0: zero group stats ----------------
__global__ void k0_zero() {
    int i = threadIdx.x;
    if (i < NB * NG) { g_sum[i] = 0.f; g_sq[i] = 0.f; }
}

// ---------------- k1: cv1 (64->32) + BN + ReLU ----------------
__global__ void k1_cv1(const float* __restrict__ x, const float* __restrict__ w1,
                       const float* __restrict__ s1, const float* __restrict__ b1) {
    __shared__ float ws[CM * CIN];   // 2048
    __shared__ float ss[CM], bs[CM];
    int t = threadIdx.x;
    for (int i = t; i < CM * CIN; i += blockDim.x) ws[i] = w1[i];
    if (t < CM) { ss[t] = s1[t]; bs[t] = b1[t]; }
    __syncthreads();

    int gid = blockIdx.x * blockDim.x + t;          // 0..NB*S-1
    int b = gid >> 15;
    int s = gid & (S - 1);

    float acc[CM];
#pragma unroll
    for (int o = 0; o < CM; o++) acc[o] = 0.f;
    const float* xb = x + b * CIN * S + s;
    for (int c = 0; c < CIN; c++) {
        float xv = xb[c * S];
#pragma unroll
        for (int o = 0; o < CM; o++) acc[o] += ws[o * CIN + c] * xv;
    }
    float* ab = g_a1 + b * CM * S + s;
#pragma unroll
    for (int o = 0; o < CM; o++) {
        float v = acc[o] * ss[o] + bs[o];
        ab[o * S] = v > 0.f ? v : 0.f;
    }
}

// ---------------- k2: depthwise 5x5x5 (zero pad) + BN ----------------
// one thread per (b, c, d, h): computes a full w-strip of 32 outputs.
__global__ void k2_dw5(const float* __restrict__ w2, const float* __restrict__ s2,
                       const float* __restrict__ b2) {
    int gid = blockIdx.x * blockDim.x + threadIdx.x;  // 0..65535
    int h = gid & 31;
    int d = (gid >> 5) & 31;
    int c = (gid >> 10) & 31;
    int b = gid >> 15;

    float acc[32];
#pragma unroll
    for (int w = 0; w < 32; w++) acc[w] = 0.f;

    const float* src = g_a1 + (b * CM + c) * S;
    const float* wc  = w2 + c * 125;

    for (int dd = 0; dd < 5; dd++) {
        int zd = d + dd - 2;
        if (zd < 0 || zd >= 32) continue;
        for (int dh = 0; dh < 5; dh++) {
            int zh = h + dh - 2;
            if (zh < 0 || zh >= 32) continue;
            const float* row = src + (zd * 32 + zh) * 32;
            float rw[32];
#pragma unroll
            for (int i = 0; i < 8; i++) {
                float4 v = *(const float4*)(row + i * 4);
                rw[i * 4 + 0] = v.x; rw[i * 4 + 1] = v.y;
                rw[i * 4 + 2] = v.z; rw[i * 4 + 3] = v.w;
            }
            const float* wr = wc + (dd * 5 + dh) * 5;
#pragma unroll
            for (int dw = 0; dw < 5; dw++) {
                float tap = wr[dw];
#pragma unroll
                for (int w = 0; w < 32; w++) {
                    int idx = w + dw - 2;
                    if (idx >= 0 && idx < 32) acc[w] += tap * rw[idx];
                }
            }
        }
    }
    float sc = s2[c], bi = b2[c];
    float* dst = g_a2 + (b * CM + c) * S + (d * 32 + h) * 32;
#pragma unroll
    for (int w = 0; w < 32; w++) dst[w] = acc[w] * sc + bi;
}

// ---------------- k3: cv3 (32->32)+BN+ReLU, cv4 (32->216)+b4, GN partial sums --
__global__ void k3_cv34(const float* __restrict__ w3, const float* __restrict__ s3,
                        const float* __restrict__ b3, const float* __restrict__ w4,
                        const float* __restrict__ b4) {
    __shared__ float w3s[CM * CM];     // 1024
    __shared__ float w4s[KCH * CM];    // 6912
    __shared__ float b4s[KCH];
    __shared__ float red[2 * NG];
    int t = threadIdx.x;
    for (int i = t; i < CM * CM; i += blockDim.x)  w3s[i] = w3[i];
    for (int i = t; i < KCH * CM; i += blockDim.x) w4s[i] = w4[i];
    for (int i = t; i < KCH; i += blockDim.x)      b4s[i] = b4[i];
    if (t < 2 * NG) red[t] = 0.f;
    __syncthreads();

    int gid = blockIdx.x * blockDim.x + t;
    int b = gid >> 15;
    int s = gid & (S - 1);

    // cv3 + bn + relu, result in registers
    float a3[CM];
#pragma unroll
    for (int o = 0; o < CM; o++) a3[o] = 0.f;
    const float* src = g_a2 + b * CM * S + s;
    for (int c = 0; c < CM; c++) {
        float v = src[c * S];
#pragma unroll
        for (int o = 0; o < CM; o++) a3[o] += w3s[o * CM + c] * v;
    }
#pragma unroll
    for (int o = 0; o < CM; o++) {
        float v = a3[o] * __ldg(s3 + o) + __ldg(b3 + o);
        a3[o] = v > 0.f ? v : 0.f;
    }

    // cv4: 216 outputs streamed, + per-group stats
    float* dst = g_wk + b * KCH * S + s;
    for (int g = 0; g < NG; g++) {
        float su = 0.f, sq = 0.f;
        for (int k = 0; k < 27; k++) {
            int kk = g * 27 + k;
            float acc = b4s[kk];
            const float* wr = w4s + kk * CM;
#pragma unroll
            for (int c = 0; c < CM; c++) acc += wr[c] * a3[c];
            dst[kk * S] = acc;
            su += acc;
            sq += acc * acc;
        }
        // warp reduce
#pragma unroll
        for (int off = 16; off; off >>= 1) {
            su += __shfl_down_sync(0xffffffffu, su, off);
            sq += __shfl_down_sync(0xffffffffu, sq, off);
        }
        if ((t & 31) == 0) {
            atomicAdd(&red[g], su);
            atomicAdd(&red[NG + g], sq);
        }
    }
    __syncthreads();
    if (t < NG) {
        atomicAdd(&g_sum[b * NG + t], red[t]);
        atomicAdd(&g_sq [b * NG + t], red[NG + t]);
    }
}

// ---------------- k4: finalize GN stats ----------------
__global__ void k4_stats() {
    int i = threadIdx.x;
    if (i < NB * NG) {
        float n  = 27.f * (float)S;
        float mu = g_sum[i] / n;
        float var = g_sq[i] / n - mu * mu;
        g_mu[i] = mu;
        g_rstd[i] = rsqrtf(var + 1e-5f);
    }
}

// ---------------- k5: GN affine + SKA (circular) + BN + residual -> y ------
// one thread per (b, g, s); loops over the 8 channels of the group.
__global__ void k5_ska(const float* __restrict__ x,
                       const float* __restrict__ gn_g, const float* __restrict__ gn_b,
                       const float* __restrict__ bn_s, const float* __restrict__ bn_b) {
    int gid = blockIdx.x * blockDim.x + threadIdx.x;  // 0..NB*NG*S-1
    int s = gid & (S - 1);
    int g = (gid >> 15) & (NG - 1);
    int b = gid >> 18;

    int d = s >> 10, h = (s >> 5) & 31, w = s & 31;

    // circular neighbor offsets (jnp.roll semantics)
    int offs[27];
    {
        int k = 0;
#pragma unroll
        for (int di = -1; di <= 1; di++) {
            int d2 = (d + di) & 31;
#pragma unroll
            for (int hi = -1; hi <= 1; hi++) {
                int h2 = (h + hi) & 31;
#pragma unroll
                for (int wi = -1; wi <= 1; wi++) {
                    int w2 = (w + wi) & 31;
                    offs[k++] = (d2 * 32 + h2) * 32 + w2;
                }
            }
        }
    }

    float mu = g_mu[b * NG + g], rs = g_rstd[b * NG + g];
    const float* wsrc = g_wk + (b * KCH + g * 27) * S + s;
    float wkv[27];
#pragma unroll
    for (int k = 0; k < 27; k++) {
        int ch = g * 27 + k;
        wkv[k] = (wsrc[k * S] - mu) * rs * __ldg(gn_g + ch) + __ldg(gn_b + ch);
    }

    const float* xb = x + (b * CIN + g * CPG) * S;
    float* yb = g_y + (b * CIN + g * CPG) * S;
    for (int c = 0; c < CPG; c++) {
        const float* xc = xb + c * S;
        float acc = 0.f;
#pragma unroll
        for (int k = 0; k < 27; k++) acc += wkv[k] * __ldg(xc + offs[k]);
        int ch = g * CPG + c;
        yb[c * S + s] = acc * __ldg(bn_s + ch) + __ldg(bn_b + ch) + xc[s];
    }
}

// ---------------- k6a: pw1 (64->128) + BN + ReLU ----------------
__global__ void k6a_pw1(const float* __restrict__ w, const float* __restrict__ sc,
                        const float* __restrict__ bi) {
    __shared__ float ws[128 * 64];   // 32 KB
    int t = threadIdx.x;
    for (int i = t; i < 128 * 64; i += blockDim.x) ws[i] = w[i];
    __syncthreads();

    int gid = blockIdx.x * blockDim.x + t;
    int b = gid >> 15;
    int s = gid & (S - 1);

    float y[CIN];
    const float* yb = g_y + b * CIN * S + s;
#pragma unroll
    for (int c = 0; c < CIN; c++) y[c] = yb[c * S];

    float* hb = g_h + b * 128 * S + s;
    for (int o = 0; o < 128; o++) {
        float acc = 0.f;
        const float* wr = ws + o * 64;
#pragma unroll
        for (int c = 0; c < CIN; c++) acc += wr[c] * y[c];
        float v = acc * __ldg(sc + o) + __ldg(bi + o);
        hb[o * S] = v > 0.f ? v : 0.f;
    }
}

// ---------------- k6b: pw2 (128->64) + BN + add y -> out ----------------
__global__ void k6b_pw2(const float* __restrict__ w, const float* __restrict__ sc,
                        const float* __restrict__ bi, float* __restrict__ out) {
    __shared__ float ws[128 * 64];   // transposed: ws[o*64+c] = w[c*128+o]
    int t = threadIdx.x;
    for (int i = t; i < 128 * 64; i += blockDim.x) {
        int o = i >> 6, c = i & 63;
        ws[i] = w[c * 128 + o];
    }
    __syncthreads();

    int gid = blockIdx.x * blockDim.x + t;
    int b = gid >> 15;
    int s = gid & (S - 1);

    float f[CIN];
#pragma unroll
    for (int c = 0; c < CIN; c++) f[c] = 0.f;

    const float* hb = g_h + b * 128 * S + s;
    for (int o = 0; o < 128; o++) {
        float hv = hb[o * S];
        const float* wr = ws + o * 64;
#pragma unroll
        for (int c = 0; c < CIN; c++) f[c] += wr[c] * hv;
    }

    const float* yb = g_y + b * CIN * S + s;
    float* ob = out + b * CIN * S + s;
#pragma unroll
    for (int c = 0; c < CIN; c++)
        ob[c * S] = yb[c * S] + f[c] * __ldg(sc + c) + __ldg(bi + c);
}

// ---------------- launcher ----------------
extern "C" void kernel_launch(void* const* d_in, const int* in_sizes, int n_in,
                              void* d_out, int out_size) {
    const float* x     = (const float*)d_in[0];
    const float* w1    = (const float*)d_in[1];
    const float* s1    = (const float*)d_in[2];
    const float* b1    = (const float*)d_in[3];
    const float* w2    = (const float*)d_in[4];
    const float* s2    = (const float*)d_in[5];
    const float* b2    = (const float*)d_in[6];
    const float* w3    = (const float*)d_in[7];
    const float* s3    = (const float*)d_in[8];
    const float* b3    = (const float*)d_in[9];
    const float* w4    = (const float*)d_in[10];
    const float* b4    = (const float*)d_in[11];
    const float* gn_g  = (const float*)d_in[12];
    const float* gn_b  = (const float*)d_in[13];
    const float* bn_s  = (const float*)d_in[14];
    const float* bn_b  = (const float*)d_in[15];
    const float* pw1_w = (const float*)d_in[16];
    const float* pw1_s = (const float*)d_in[17];
    const float* pw1_b = (const float*)d_in[18];
    const float* pw2_w = (const float*)d_in[19];
    const float* pw2_s = (const float*)d_in[20];
    const float* pw2_b = (const float*)d_in[21];
    float* out = (float*)d_out;

    k0_zero <<<1, 32>>>();
    k1_cv1  <<<512, 128>>>(x, w1, s1, b1);           // NB*S threads
    k2_dw5  <<<256, 256>>>(w2, s2, b2);              // NB*CM*32*32 threads
    k3_cv34 <<<512, 128>>>(w3, s3, b3, w4, b4);      // NB*S threads
    k4_stats<<<1, 32>>>();
    k5_ska  <<<2048, 256>>>(x, gn_g, gn_b, bn_s, bn_b); // NB*NG*S threads
    k6a_pw1 <<<512, 128>>>(pw1_w, pw1_s, pw1_b);     // NB*S threads
    k6b_pw2 <<<512, 128>>>(pw2_w, pw2_s, pw2_b, out);
}

// round 3
// speedup vs baseline: 1.0917x; 1.0917x over previous
#include <cuda_runtime.h>

#define S   32768          // 32*32*32 spatial
#define NB  2              // batch
#define CIN 64
#define CM  32             // mid channels
#define KCH 216            // dynamic kernel channels
#define NG  8              // groups
#define CPG 8              // channels per group (64/8)

typedef unsigned long long u64;

// ---------------- f32x2 helpers ----------------
__device__ __forceinline__ u64 pk2(float a, float b) {
    u64 r; asm("mov.b64 %0,{%1,%2};" : "=l"(r) : "f"(a), "f"(b)); return r;
}
__device__ __forceinline__ void upk2(u64 v, float& a, float& b) {
    asm("mov.b64 {%0,%1},%2;" : "=f"(a), "=f"(b) : "l"(v));
}
__device__ __forceinline__ void fma2(u64& d, u64 a, u64 b) {
    asm("fma.rn.f32x2 %0,%1,%2,%0;" : "+l"(d) : "l"(a), "l"(b));
}
__device__ __forceinline__ void add2(u64& d, u64 a) {
    asm("add.rn.f32x2 %0,%1,%0;" : "+l"(d) : "l"(a));
}

// ---------------- scratch (device globals; allocation-free) ----------------
__device__ float g_a1[NB * CM  * S];   // cv1 out; later reused for cv3 out (a3)
__device__ float g_a2[NB * CM  * S];   // after dw5+bn
__device__ float g_wk[NB * KCH * S];   // cv4 output (pre-GN)
__device__ float g_y [NB * CIN * S];   // after SKA + bn + residual
__device__ float g_h [NB * 128 * S];   // FFN hidden
__device__ float g_sum[NB * NG];
__device__ float g_sq [NB * NG];
__device__ float g_mu [NB * NG];
__device__ float g_rstd[NB * NG];

// ---------------- k0: zero group stats ----------------
__global__ void k0_zero() {
    int i = threadIdx.x;
    if (i < NB * NG) { g_sum[i] = 0.f; g_sq[i] = 0.f; }
}

// ---------------- k1: cv1 (64->32) + BN + ReLU ----------------
// block 128 = 2 output-groups x 64 slots; 4 positions per thread.
__global__ void k1_cv1(const float* __restrict__ x, const float* __restrict__ w1,
                       const float* __restrict__ s1, const float* __restrict__ b1) {
    __shared__ u64 ws[CM * CIN];     // packed {w,w}, 16KB
    int t = threadIdx.x;
    for (int i = t; i < CM * CIN; i += 128) { float w = w1[i]; ws[i] = pk2(w, w); }
    __syncthreads();

    int og = t >> 6, slot = t & 63;
    int pos = blockIdx.x * 256 + slot * 4;
    int b = pos >> 15, s = pos & (S - 1);

    u64 aL[16], aH[16];
#pragma unroll
    for (int o = 0; o < 16; o++) { aL[o] = 0ull; aH[o] = 0ull; }

    const float* xb = x + b * CIN * S + s;
    for (int c = 0; c < CIN; c++) {
        ulonglong2 xq = *(const ulonglong2*)(xb + c * S);
#pragma unroll
        for (int o = 0; o < 16; o++) {
            u64 wv = ws[(og * 16 + o) * CIN + c];
            fma2(aL[o], wv, xq.x);
            fma2(aH[o], wv, xq.y);
        }
    }
#pragma unroll
    for (int o = 0; o < 16; o++) {
        int oo = og * 16 + o;
        float sc = __ldg(s1 + oo), bb = __ldg(b1 + oo);
        float a0, a1v, a2v, a3v;
        upk2(aL[o], a0, a1v); upk2(aH[o], a2v, a3v);
        float4 r;
        r.x = fmaxf(a0  * sc + bb, 0.f);
        r.y = fmaxf(a1v * sc + bb, 0.f);
        r.z = fmaxf(a2v * sc + bb, 0.f);
        r.w = fmaxf(a3v * sc + bb, 0.f);
        *(float4*)(g_a1 + (b * CM + oo) * S + s) = r;
    }
}

// ---------------- k2: depthwise 5x5x5 (zero pad) + BN ----------------
__global__ void k2_dw5(const float* __restrict__ w2, const float* __restrict__ s2,
                       const float* __restrict__ b2) {
    int gid = blockIdx.x * blockDim.x + threadIdx.x;  // 0..65535
    int h = gid & 31;
    int d = (gid >> 5) & 31;
    int c = (gid >> 10) & 31;
    int b = gid >> 15;

    float acc[32];
#pragma unroll
    for (int w = 0; w < 32; w++) acc[w] = 0.f;

    const float* src = g_a1 + (b * CM + c) * S;
    const float* wc  = w2 + c * 125;

    for (int dd = 0; dd < 5; dd++) {
        int zd = d + dd - 2;
        if (zd < 0 || zd >= 32) continue;
        for (int dh = 0; dh < 5; dh++) {
            int zh = h + dh - 2;
            if (zh < 0 || zh >= 32) continue;
            const float* row = src + (zd * 32 + zh) * 32;
            float rw[32];
#pragma unroll
            for (int i = 0; i < 8; i++) {
                float4 v = *(const float4*)(row + i * 4);
                rw[i * 4 + 0] = v.x; rw[i * 4 + 1] = v.y;
                rw[i * 4 + 2] = v.z; rw[i * 4 + 3] = v.w;
            }
            const float* wr = wc + (dd * 5 + dh) * 5;
#pragma unroll
            for (int dw = 0; dw < 5; dw++) {
                float tap = wr[dw];
#pragma unroll
                for (int w = 0; w < 32; w++) {
                    int idx = w + dw - 2;
                    if (idx >= 0 && idx < 32) acc[w] += tap * rw[idx];
                }
            }
        }
    }
    float sc = s2[c], bi = b2[c];
    float* dst = g_a2 + (b * CM + c) * S + (d * 32 + h) * 32;
#pragma unroll
    for (int w = 0; w < 32; w++) dst[w] = acc[w] * sc + bi;
}

// ---------------- k3a: cv3 (32->32) + BN + ReLU -> g_a1 (reuse) ----------------
__global__ void k3a_cv3(const float* __restrict__ w3, const float* __restrict__ s3,
                        const float* __restrict__ b3) {
    __shared__ u64 ws[CM * CM];      // 8KB
    int t = threadIdx.x;
    for (int i = t; i < CM * CM; i += 128) { float w = w3[i]; ws[i] = pk2(w, w); }
    __syncthreads();

    int og = t >> 6, slot = t & 63;
    int pos = blockIdx.x * 256 + slot * 4;
    int b = pos >> 15, s = pos & (S - 1);

    u64 aL[16], aH[16];
#pragma unroll
    for (int o = 0; o < 16; o++) { aL[o] = 0ull; aH[o] = 0ull; }

    const float* xb = g_a2 + b * CM * S + s;
    for (int c = 0; c < CM; c++) {
        ulonglong2 xq = *(const ulonglong2*)(xb + c * S);
#pragma unroll
        for (int o = 0; o < 16; o++) {
            u64 wv = ws[(og * 16 + o) * CM + c];
            fma2(aL[o], wv, xq.x);
            fma2(aH[o], wv, xq.y);
        }
    }
#pragma unroll
    for (int o = 0; o < 16; o++) {
        int oo = og * 16 + o;
        float sc = __ldg(s3 + oo), bb = __ldg(b3 + oo);
        float a0, a1v, a2v, a3v;
        upk2(aL[o], a0, a1v); upk2(aH[o], a2v, a3v);
        float4 r;
        r.x = fmaxf(a0  * sc + bb, 0.f);
        r.y = fmaxf(a1v * sc + bb, 0.f);
        r.z = fmaxf(a2v * sc + bb, 0.f);
        r.w = fmaxf(a3v * sc + bb, 0.f);
        *(float4*)(g_a1 + (b * CM + oo) * S + s) = r;
    }
}

// ---------------- k3b: cv4 (32->216) + b4 + GN partial sums ----------------
// block 128 = 8 groups x 16 slots; 4 positions per thread; one group per thread.
__global__ void k3b_cv4(const float* __restrict__ w4, const float* __restrict__ b4) {
    extern __shared__ u64 sm[];
    u64* w4p = sm;                 // 216*32
    u64* b4p = sm + KCH * CM;      // 216
    int t = threadIdx.x;
    for (int i = t; i < KCH * CM; i += 128) { float w = w4[i]; w4p[i] = pk2(w, w); }
    for (int i = t; i < KCH; i += 128)      { float w = b4[i]; b4p[i] = pk2(w, w); }
    __shared__ float redsum[NG], redsq[NG];
    if (t < NG) { redsum[t] = 0.f; redsq[t] = 0.f; }
    __syncthreads();

    int g = t >> 4, slot = t & 15;
    int pos = blockIdx.x * 64 + slot * 4;
    int b = pos >> 15, s = pos & (S - 1);

    // stage all 32 a3 values (4 positions each) in registers
    ulonglong2 aq[CM];
    const float* src = g_a1 + b * CM * S + s;
#pragma unroll
    for (int c = 0; c < CM; c++) aq[c] = *(const ulonglong2*)(src + c * S);

    u64 suL = 0ull, suH = 0ull, sqL = 0ull, sqH = 0ull;
    float* dst = g_wk + b * KCH * S + s;
    for (int k = 0; k < 27; k++) {
        int kk = g * 27 + k;
        u64 L = b4p[kk], H = b4p[kk];
        const u64* wr = w4p + kk * CM;
#pragma unroll
        for (int c = 0; c < CM; c++) {
            u64 wv = wr[c];
            fma2(L, wv, aq[c].x);
            fma2(H, wv, aq[c].y);
        }
        ulonglong2 o; o.x = L; o.y = H;
        *(ulonglong2*)(dst + kk * S) = o;
        add2(suL, L); add2(suH, H);
        fma2(sqL, L, L); fma2(sqH, H, H);
    }
    float x0, x1, x2, x3;
    upk2(suL, x0, x1); upk2(suH, x2, x3);
    float su = x0 + x1 + x2 + x3;
    upk2(sqL, x0, x1); upk2(sqH, x2, x3);
    float sq = x0 + x1 + x2 + x3;
    atomicAdd(&redsum[g], su);
    atomicAdd(&redsq[g], sq);
    __syncthreads();
    if (t < NG) {
        atomicAdd(&g_sum[b * NG + t], redsum[t]);
        atomicAdd(&g_sq [b * NG + t], redsq[t]);
    }
}

// ---------------- k4: finalize GN stats ----------------
__global__ void k4_stats() {
    int i = threadIdx.x;
    if (i < NB * NG) {
        float n  = 27.f * (float)S;
        float mu = g_sum[i] / n;
        float var = g_sq[i] / n - mu * mu;
        g_mu[i] = mu;
        g_rstd[i] = rsqrtf(var + 1e-5f);
    }
}

// ---------------- k5: GN affine + SKA (circular) + BN + residual -> y ------
// thread = (b, g, d, h, wq); 4 consecutive w outputs per thread.
__global__ void k5_ska(const float* __restrict__ x,
                       const float* __restrict__ gn_g, const float* __restrict__ gn_b,
                       const float* __restrict__ bn_s, const float* __restrict__ bn_b) {
    int gid = blockIdx.x * blockDim.x + threadIdx.x;   // 0 .. 131071
    int wq = gid & 7;
    int h  = (gid >> 3) & 31;
    int d  = (gid >> 8) & 31;
    int g  = (gid >> 13) & 7;
    int b  = gid >> 16;
    int w0 = wq * 4;
    int sbase = (d * 32 + h) * 32 + w0;

    float mu = g_mu[b * NG + g], rs = g_rstd[b * NG + g];

    // dynamic kernel values, GN-affined, packed as f32x2 pairs
    u64 kvL[27], kvH[27];
    const float* wsrc = g_wk + (b * KCH + g * 27) * S + sbase;
#pragma unroll
    for (int k = 0; k < 27; k++) {
        float4 q = *(const float4*)(wsrc + k * S);
        int ch = g * 27 + k;
        float gg = __ldg(gn_g + ch) * rs;
        float bb = __ldg(gn_b + ch) - mu * gg;
        kvL[k] = pk2(q.x * gg + bb, q.y * gg + bb);
        kvH[k] = pk2(q.z * gg + bb, q.w * gg + bb);
    }

    const float* xg = x + (b * CIN + g * CPG) * S;
    float* yg = g_y + (b * CIN + g * CPG) * S;

    for (int c = 0; c < CPG; c++) {
        const float* xc = xg + c * S;
        u64 aL = 0ull, aH = 0ull;
        int k = 0;
#pragma unroll
        for (int di = -1; di <= 1; di++) {
            int zd = (d + di) & 31;
#pragma unroll
            for (int hi = -1; hi <= 1; hi++) {
                int zh = (h + hi) & 31;
                const float* row = xc + (zd * 32 + zh) * 32;
                float4 mid = *(const float4*)(row + w0);     // v1..v4
                float v0 = row[(w0 - 1) & 31];
                float v5 = row[(w0 + 4) & 31];
                u64 p01 = pk2(v0,    mid.x);
                u64 p12 = pk2(mid.x, mid.y);
                u64 p23 = pk2(mid.y, mid.z);
                u64 p34 = pk2(mid.z, mid.w);
                u64 p45 = pk2(mid.w, v5);
                fma2(aL, kvL[k + 0], p01); fma2(aH, kvH[k + 0], p23);
                fma2(aL, kvL[k + 1], p12); fma2(aH, kvH[k + 1], p34);
                fma2(aL, kvL[k + 2], p23); fma2(aH, kvH[k + 2], p45);
                k += 3;
            }
        }
        float a0, a1v, a2v, a3v;
        upk2(aL, a0, a1v); upk2(aH, a2v, a3v);
        int ch = g * CPG + c;
        float bs_ = __ldg(bn_s + ch), bb_ = __ldg(bn_b + ch);
        float4 xq = *(const float4*)(xc + sbase);
        float4 r;
        r.x = a0  * bs_ + bb_ + xq.x;
        r.y = a1v * bs_ + bb_ + xq.y;
        r.z = a2v * bs_ + bb_ + xq.z;
        r.w = a3v * bs_ + bb_ + xq.w;
        *(float4*)(yg + c * S + sbase) = r;
    }
}

// ---------------- k6a: pw1 (64->128) + BN + ReLU ----------------
// block 256 = 8 output-groups x 32 slots; 4 positions per thread.
__global__ void k6a_pw1(const float* __restrict__ w, const float* __restrict__ sc,
                        const float* __restrict__ bi) {
    extern __shared__ u64 sm[];
    u64* ws = sm;                  // 128*64 packed
    u64* sp = sm + 128 * 64;       // 128
    u64* bp = sp + 128;            // 128
    int t = threadIdx.x;
    for (int i = t; i < 128 * 64; i += 256) { float v = w[i]; ws[i] = pk2(v, v); }
    for (int i = t; i < 128; i += 256) {
        sp[i] = pk2(sc[i], sc[i]);
        bp[i] = pk2(bi[i], bi[i]);
    }
    __syncthreads();

    int og = t >> 5, slot = t & 31;
    int pos = blockIdx.x * 128 + slot * 4;
    int b = pos >> 15, s = pos & (S - 1);

    u64 aL[16], aH[16];
#pragma unroll
    for (int o = 0; o < 16; o++) { aL[o] = 0ull; aH[o] = 0ull; }

    const float* yb = g_y + b * CIN * S + s;
    for (int c = 0; c < CIN; c++) {
        ulonglong2 yq = *(const ulonglong2*)(yb + c * S);
#pragma unroll
        for (int o = 0; o < 16; o++) {
            u64 wv = ws[(og * 16 + o) * CIN + c];
            fma2(aL[o], wv, yq.x);
            fma2(aH[o], wv, yq.y);
        }
    }
#pragma unroll
    for (int o = 0; o < 16; o++) {
        int oo = og * 16 + o;
        u64 rL = bp[oo], rH = bp[oo];
        fma2(rL, aL[o], sp[oo]);
        fma2(rH, aH[o], sp[oo]);
        float a0, a1v, a2v, a3v;
        upk2(rL, a0, a1v); upk2(rH, a2v, a3v);
        float4 r;
        r.x = fmaxf(a0,  0.f); r.y = fmaxf(a1v, 0.f);
        r.z = fmaxf(a2v, 0.f); r.w = fmaxf(a3v, 0.f);
        *(float4*)(g_h + (b * 128 + oo) * S + s) = r;
    }
}

// ---------------- k6b: pw2 (128->64) + BN + add y -> out ----------------
// block 256 = 4 output-groups x 64 slots; 4 positions per thread.
__global__ void k6b_pw2(const float* __restrict__ w, const float* __restrict__ sc,
                        const float* __restrict__ bi, float* __restrict__ out) {
    extern __shared__ u64 sm[];
    u64* ws = sm;                  // [o<64][c<128] packed, straight copy of (64,128)
    int t = threadIdx.x;
    for (int i = t; i < 64 * 128; i += 256) {
        float v = w[i];            // pw2_w is [out=64][in=128] row-major already
        ws[i] = pk2(v, v);
    }
    __syncthreads();

    int og = t >> 6, slot = t & 63;
    int pos = blockIdx.x * 256 + slot * 4;
    int b = pos >> 15, s = pos & (S - 1);

    u64 aL[16], aH[16];
#pragma unroll
    for (int o = 0; o < 16; o++) { aL[o] = 0ull; aH[o] = 0ull; }

    const float* hb = g_h + b * 128 * S + s;
    for (int c = 0; c < 128; c++) {
        ulonglong2 hq = *(const ulonglong2*)(hb + c * S);
#pragma unroll
        for (int o = 0; o < 16; o++) {
            u64 wv = ws[(og * 16 + o) * 128 + c];
            fma2(aL[o], wv, hq.x);
            fma2(aH[o], wv, hq.y);
        }
    }
    const float* yb = g_y + b * CIN * S + s;
#pragma unroll
    for (int o = 0; o < 16; o++) {
        int oo = og * 16 + o;
        float scv = __ldg(sc + oo), biv = __ldg(bi + oo);
        float a0, a1v, a2v, a3v;
        upk2(aL[o], a0, a1v); upk2(aH[o], a2v, a3v);
        float4 yq = *(const float4*)(yb + oo * S);
        float4 r;
        r.x = yq.x + a0  * scv + biv;
        r.y = yq.y + a1v * scv + biv;
        r.z = yq.z + a2v * scv + biv;
        r.w = yq.w + a3v * scv + biv;
        *(float4*)(out + (b * CIN + oo) * S + s) = r;
    }
}

// ---------------- launcher ----------------
extern "C" void kernel_launch(void* const* d_in, const int* in_sizes, int n_in,
                              void* d_out, int out_size) {
    const float* x     = (const float*)d_in[0];
    const float* w1    = (const float*)d_in[1];
    const float* s1    = (const float*)d_in[2];
    const float* b1    = (const float*)d_in[3];
    const float* w2    = (const float*)d_in[4];
    const float* s2    = (const float*)d_in[5];
    const float* b2    = (const float*)d_in[6];
    const float* w3    = (const float*)d_in[7];
    const float* s3    = (const float*)d_in[8];
    const float* b3    = (const float*)d_in[9];
    const float* w4    = (const float*)d_in[10];
    const float* b4    = (const float*)d_in[11];
    const float* gn_g  = (const float*)d_in[12];
    const float* gn_b  = (const float*)d_in[13];
    const float* bn_s  = (const float*)d_in[14];
    const float* bn_b  = (const float*)d_in[15];
    const float* pw1_w = (const float*)d_in[16];
    const float* pw1_s = (const float*)d_in[17];
    const float* pw1_b = (const float*)d_in[18];
    const float* pw2_w = (const float*)d_in[19];
    const float* pw2_s = (const float*)d_in[20];
    const float* pw2_b = (const float*)d_in[21];
    float* out = (float*)d_out;

    const int smem_k3b = (KCH * CM + KCH) * 8;       // 55.5KB + 1.7KB
    const int smem_k6a = (128 * 64 + 256) * 8;       // 66KB
    const int smem_k6b = (64 * 128) * 8;             // 64KB
    cudaFuncSetAttribute(k3b_cv4, cudaFuncAttributeMaxDynamicSharedMemorySize, smem_k3b);
    cudaFuncSetAttribute(k6a_pw1, cudaFuncAttributeMaxDynamicSharedMemorySize, smem_k6a);
    cudaFuncSetAttribute(k6b_pw2, cudaFuncAttributeMaxDynamicSharedMemorySize, smem_k6b);

    k0_zero <<<1, 32>>>();
    k1_cv1  <<<256, 128>>>(x, w1, s1, b1);                    // 2 og x 64 slots
    k2_dw5  <<<256, 256>>>(w2, s2, b2);
    k3a_cv3 <<<256, 128>>>(w3, s3, b3);
    k3b_cv4 <<<1024, 128, smem_k3b>>>(w4, b4);
    k4_stats<<<1, 32>>>();
    k5_ska  <<<1024, 128>>>(x, gn_g, gn_b, bn_s, bn_b);       // 131072 threads
    k6a_pw1 <<<512, 256, smem_k6a>>>(pw1_w, pw1_s, pw1_b);
    k6b_pw2 <<<256, 256, smem_k6b>>>(pw2_w, pw2_s, pw2_b, out);
}